// round 13
// baseline (speedup 1.0000x reference)
#include <cuda_runtime.h>
#include <cuda_bf16.h>
#include <math.h>
#include <stdint.h>

#define DIMK 128
#define RQ   131072
#define BB   1024
#define NN   10
#define NM   (BB*NN)          /* 10240 */
#define INVT 10.0f
#define NSPL1 16              /* phase-1 R splits: 8192 cols, 64 tiles each */
#define NT1   64
#define NSPL2 10              /* phase-2 splits: 1024 cols, 8 tiles each */
#define NT2   8

#define SMEM1 98304           /* A 32K + B double buffer 2x32K */
#define SMEM2 65536           /* A 32K + B 32K */

/* ------------------------- asm helpers ---------------------------- */
__device__ __forceinline__ uint32_t smem_u32(const void* p) {
    uint32_t a;
    asm("{ .reg .u64 t; cvta.to.shared.u64 t, %1; cvt.u32.u64 %0, t; }"
        : "=r"(a) : "l"(p));
    return a;
}
#define LDSM4(r0,r1,r2,r3, a) \
    asm volatile("ldmatrix.sync.aligned.m8n8.x4.shared.b16 {%0,%1,%2,%3}, [%4];" \
        : "=r"(r0),"=r"(r1),"=r"(r2),"=r"(r3) : "r"(a))
#define LDSM4T(r0,r1,r2,r3, a) \
    asm volatile("ldmatrix.sync.aligned.m8n8.x4.trans.shared.b16 {%0,%1,%2,%3}, [%4];" \
        : "=r"(r0),"=r"(r1),"=r"(r2),"=r"(r3) : "r"(a))
#define MMA16816(c0,c1,c2,c3, a0,a1,a2,a3, b0,b1) \
    asm volatile("mma.sync.aligned.m16n8k16.row.col.f32.bf16.bf16.f32 " \
        "{%0,%1,%2,%3}, {%4,%5,%6,%7}, {%8,%9}, {%0,%1,%2,%3};" \
        : "+f"(c0),"+f"(c1),"+f"(c2),"+f"(c3) \
        : "r"(a0),"r"(a1),"r"(a2),"r"(a3),"r"(b0),"r"(b1))
#define CPA16(dst, src) \
    asm volatile("cp.async.cg.shared.global [%0], [%1], 16;" \
        :: "r"(dst), "l"(src) : "memory")
#define CPA_COMMIT() asm volatile("cp.async.commit_group;" ::: "memory")
#define CPA_WAIT0()  asm volatile("cp.async.wait_group 0;" ::: "memory")

#define INS(V, IX, s, c) do {                                          \
    if ((s) > V[9]) {                                                  \
        V[9] = (s); IX[9] = (c);                                       \
        _Pragma("unroll")                                              \
        for (int _j = 9; _j > 0; _j--)                                 \
            if (V[_j] > V[_j-1]) {                                     \
                float _t = V[_j]; V[_j] = V[_j-1]; V[_j-1] = _t;       \
                int _ti = IX[_j]; IX[_j] = IX[_j-1]; IX[_j-1] = _ti;   \
            }                                                          \
    } } while (0)

__device__ __forceinline__ uint4 cvt8(float4 a, float4 b) {
    __nv_bfloat162 p0 = __float22bfloat162_rn(make_float2(a.x, a.y));
    __nv_bfloat162 p1 = __float22bfloat162_rn(make_float2(a.z, a.w));
    __nv_bfloat162 p2 = __float22bfloat162_rn(make_float2(b.x, b.y));
    __nv_bfloat162 p3 = __float22bfloat162_rn(make_float2(b.z, b.w));
    uint4 u;
    u.x = *(uint32_t*)&p0; u.y = *(uint32_t*)&p1;
    u.z = *(uint32_t*)&p2; u.w = *(uint32_t*)&p3;
    return u;
}

/* -------------------------- scratch ------------------------------- */
__device__ float g_fn[2][BB*DIMK];
__device__ __nv_bfloat16 g_qb[2][(size_t)DIMK*RQ];    /* g_qb[side] = CROSS queue */
__device__ float g_ptv[2048*NSPL1*NN];
__device__ int   g_pti[2048*NSPL1*NN];
__device__ int   g_topk[2*NM];
__device__ __nv_bfloat16 g_nnb[2][(size_t)NM*DIMK];   /* [m][k] bf16 */
__device__ float g_S[2048*NSPL2];
__device__ float g_pos[2*BB];

/* ------------------------------------------------------------------ */
/* 1. row-normalize feats; scatter f.T into output queue[:, :B]        */
/* ------------------------------------------------------------------ */
__global__ void k_normalize(const float* __restrict__ fX,
                            const float* __restrict__ fY,
                            float* __restrict__ out)
{
    int b = blockIdx.x, side = blockIdx.y, d = threadIdx.x;
    const float* src = side ? fY : fX;
    float v = src[b*DIMK + d];
    float ss = v*v;
    #pragma unroll
    for (int o = 16; o; o >>= 1) ss += __shfl_xor_sync(0xFFFFFFFFu, ss, o);
    __shared__ float ws[4];
    if ((d & 31) == 0) ws[d >> 5] = ss;
    __syncthreads();
    float inv = rsqrtf(ws[0] + ws[1] + ws[2] + ws[3]);
    float w = v * inv;
    g_fn[side][b*DIMK + d] = w;
    float* q = out + 1 + (size_t)side * DIMK * RQ;
    q[(size_t)d * RQ + b] = w;
}

/* ------------------------------------------------------------------ */
/* 2. prep both sides in ONE launch: bf16 CROSS-queue cache            */
/* ------------------------------------------------------------------ */
__global__ void k_prep(const float* __restrict__ qX,
                       const float* __restrict__ qY)
{
    int side = blockIdx.z, d = blockIdx.y;
    int c = 2 * (blockIdx.x * blockDim.x + threadIdx.x);
    const float* q = side ? qY : qX;
    size_t off = (size_t)d * RQ + c;
    float2 v = *(const float2*)(q + off);
    *(__nv_bfloat162*)(&g_qb[side ^ 1][off]) = __float22bfloat162_rn(v);
}

/* ------------------------------------------------------------------ */
/* 3. FUSED bf16 HMMA sim GEMM + per-row top-10 (cp.async staged B)    */
/*    + hidden fp32 queue->output copy in the MMA stall shadow         */
/* ------------------------------------------------------------------ */
__global__ void __launch_bounds__(256)
k_simtopk(const float* __restrict__ qX, const float* __restrict__ qY,
          float* __restrict__ out)
{
    extern __shared__ __align__(16) char smem[];
    const int side = blockIdx.z, mt = blockIdx.y, rs = blockIdx.x;
    const __nv_bfloat16* Q = g_qb[side];
    int tid = threadIdx.x, wid = tid >> 5, lane = tid & 31;
    uint32_t sb = smem_u32(smem);
    const uint32_t sbA = sb, sbB0 = sb + 32768, sbB1 = sb + 65536;
    const int c_cta = rs * (NT1 * 128);

    /* hidden-copy assignment: 256 CTAs <-> 256 output rows (side,d) */
    const int cta_lin = (side*8 + mt)*NSPL1 + rs;        /* 0..255 */
    const int cp_side = cta_lin >> 7, cp_d = cta_lin & 127;
    const float* csrc = (cp_side ? qY : qX) + (size_t)cp_d * RQ;
    float* cdst = out + 1 + (size_t)cp_side * DIMK * RQ + (size_t)cp_d * RQ;

    /* async-stage B tile t into dstbase (swizzled [k][n] bf16) */
    auto stage_b = [&](uint32_t dstbase, int t) {
        int c0 = c_cta + t*128;
        #pragma unroll
        for (int j = 0; j < 8; j++) {
            int idx = tid + j*256;
            int k = idx >> 4, nc = idx & 15;
            uint32_t dst = dstbase + k*256 + ((nc ^ (k & 7)))*16;
            CPA16(dst, (const void*)(Q + (size_t)k*RQ + c0 + nc*8));
        }
        CPA_COMMIT();
    };

    stage_b(sbB0, 0);                      /* B0 in flight early */

    /* stage A: g_fn[side] rows mt*128.. as bf16, swizzled [m][k] */
    const float* Af = g_fn[side] + (size_t)mt * 128 * DIMK;
    #pragma unroll
    for (int j = 0; j < 8; j++) {
        int idx = tid + j*256;
        int m = idx >> 4, kc = idx & 15;
        const float* p = Af + m*DIMK + kc*8;
        float4 f0 = *(const float4*)p;
        float4 f1 = *(const float4*)(p + 4);
        *(uint4*)(smem + m*256 + ((kc ^ (m & 7)))*16) = cvt8(f0, f1);
    }

    CPA_WAIT0();
    __syncthreads();                       /* A + B0 ready */

    /* A fragments: 8 ksteps x 4 regs */
    uint32_t a[8][4];
    {
        int m = wid*16 + (lane & 15);
        #pragma unroll
        for (int ks = 0; ks < 8; ks++) {
            int kc = ks*2 + (lane >> 4);
            uint32_t addr = sbA + m*256 + ((kc ^ (m & 7)))*16;
            LDSM4(a[ks][0], a[ks][1], a[ks][2], a[ks][3], addr);
        }
    }

    float v0[10], v1[10]; int x0[10], x1[10];
    #pragma unroll
    for (int i = 0; i < 10; i++) {
        v0[i] = -INFINITY; v1[i] = -INFINITY; x0[i] = 0; x1[i] = 0;
    }
    const int coff = 2*(lane & 3);

    for (int t = 0; t < NT1; t++) {
        uint32_t bufa = (t & 1) ? sbB1 : sbB0;
        if (t + 1 < NT1) stage_b((t & 1) ? sbB0 : sbB1, t + 1);

        /* issue hidden-copy loads early (latency covered by MMA work) */
        int cc = BB + t*2048 + tid*8;
        bool cok = (cc + 8 <= RQ);
        float4 u0, u1;
        if (cok) { u0 = *(const float4*)(csrc + cc);
                   u1 = *(const float4*)(csrc + cc + 4); }

        int cbase = c_cta + t*128 + coff;
        #pragma unroll 2
        for (int nt = 0; nt < 16; nt++) {
            uint32_t b[16];
            #pragma unroll
            for (int kb = 0; kb < 4; kb++) {
                int krow = kb*32 + lane;
                uint32_t addr = bufa + krow*256 + ((nt ^ (krow & 7)))*16;
                LDSM4T(b[kb*4+0], b[kb*4+1], b[kb*4+2], b[kb*4+3], addr);
            }
            float A0 = 0.f, A1 = 0.f, A2 = 0.f, A3 = 0.f;
            float B0 = 0.f, B1 = 0.f, B2 = 0.f, B3 = 0.f;
            #pragma unroll
            for (int ks = 0; ks < 4; ks++) {
                MMA16816(A0, A1, A2, A3,
                         a[ks][0], a[ks][1], a[ks][2], a[ks][3],
                         b[ks*2], b[ks*2+1]);
                MMA16816(B0, B1, B2, B3,
                         a[ks+4][0], a[ks+4][1], a[ks+4][2], a[ks+4][3],
                         b[(ks+4)*2], b[(ks+4)*2+1]);
            }
            float c0 = A0 + B0, c1 = A1 + B1, c2 = A2 + B2, c3 = A3 + B3;
            int col = cbase + nt*8;
            if (fmaxf(c0, c1) > v0[9]) { INS(v0, x0, c0, col); INS(v0, x0, c1, col+1); }
            if (fmaxf(c2, c3) > v1[9]) { INS(v1, x1, c2, col); INS(v1, x1, c3, col+1); }
        }

        /* hidden-copy stores (4B-aligned scalars — out+1 base) */
        if (cok) {
            cdst[cc+0] = u0.x; cdst[cc+1] = u0.y;
            cdst[cc+2] = u0.z; cdst[cc+3] = u0.w;
            cdst[cc+4] = u1.x; cdst[cc+5] = u1.y;
            cdst[cc+6] = u1.z; cdst[cc+7] = u1.w;
        }

        if (t + 1 < NT1) { CPA_WAIT0(); __syncthreads(); }
    }

    /* quad merge: lanes (l&3)=0..3 share rows g, g+8 */
    int g = lane >> 2, q = lane & 3;
    #pragma unroll
    for (int listid = 0; listid < 2; listid++) {
        float* v = listid ? v1 : v0;
        int*  ix = listid ? x1 : x0;
        int row = (side*8 + mt)*128 + wid*16 + g + listid*8;
        #pragma unroll
        for (int k = 0; k < 10; k++) {
            float bv = v[0]; int bi = ix[0]; int bq = q;
            #pragma unroll
            for (int o = 1; o <= 2; o <<= 1) {
                float ov = __shfl_xor_sync(0xFFFFFFFFu, bv, o);
                int oi = __shfl_xor_sync(0xFFFFFFFFu, bi, o);
                int oq = __shfl_xor_sync(0xFFFFFFFFu, bq, o);
                if (ov > bv || (ov == bv && oi < bi)) { bv = ov; bi = oi; bq = oq; }
            }
            if (q == 0) {
                g_ptv[((size_t)row*NSPL1 + rs)*NN + k] = bv;
                g_pti[((size_t)row*NSPL1 + rs)*NN + k] = bi;
            }
            if (q == bq) {
                #pragma unroll
                for (int j = 0; j < 9; j++) { v[j] = v[j+1]; ix[j] = ix[j+1]; }
                v[9] = -INFINITY;
            }
        }
    }
}

/* ------------------------------------------------------------------ */
/* 4. merge NSPL1=16 partial top-10 lists per row (warp per row)       */
/* ------------------------------------------------------------------ */
__global__ void k_merge()
{
    int rg = blockIdx.x * 8 + (threadIdx.x >> 5);
    int lane = threadIdx.x & 31;
    float v[10]; int ix[10];
    if (lane < NSPL1) {
        const float* pv = g_ptv + ((size_t)rg*NSPL1 + lane)*NN;
        const int*   pi = g_pti + ((size_t)rg*NSPL1 + lane)*NN;
        #pragma unroll
        for (int k = 0; k < 10; k++) { v[k] = pv[k]; ix[k] = pi[k]; }
    } else {
        #pragma unroll
        for (int k = 0; k < 10; k++) { v[k] = -INFINITY; ix[k] = 0x7FFFFFFF; }
    }
    #pragma unroll
    for (int k = 0; k < 10; k++) {
        float bv = v[0]; int bi = ix[0]; int bl = lane;
        #pragma unroll
        for (int o = 1; o <= 8; o <<= 1) {
            float ov = __shfl_xor_sync(0xFFFFFFFFu, bv, o);
            int oi = __shfl_xor_sync(0xFFFFFFFFu, bi, o);
            int ol = __shfl_xor_sync(0xFFFFFFFFu, bl, o);
            if (ov > bv || (ov == bv && oi < bi)) { bv = ov; bi = oi; bl = ol; }
        }
        if (lane == 0) g_topk[rg*NN + k] = bi;
        if (lane == bl) {
            #pragma unroll
            for (int j = 0; j < 9; j++) { v[j] = v[j+1]; ix[j] = ix[j+1]; }
            v[9] = -INFINITY;
        }
    }
}

/* ------------------------------------------------------------------ */
/* 5. gather neighbors as bf16 [m][k] (from fp32 CROSS queue)          */
/* ------------------------------------------------------------------ */
__global__ void k_gather(const float* __restrict__ qX,
                         const float* __restrict__ qY)
{
    int side = blockIdx.y;
    int m = blockIdx.x * 8 + (threadIdx.x >> 5);
    int d = (threadIdx.x & 31) * 4;
    const float* Q = side ? qX : qY;
    int idx = g_topk[side*NM + m];
    float a0 = Q[(size_t)(d+0)*RQ + idx];
    float a1 = Q[(size_t)(d+1)*RQ + idx];
    float a2 = Q[(size_t)(d+2)*RQ + idx];
    float a3 = Q[(size_t)(d+3)*RQ + idx];
    __nv_bfloat162 p0 = __float22bfloat162_rn(make_float2(a0, a1));
    __nv_bfloat162 p1 = __float22bfloat162_rn(make_float2(a2, a3));
    uint2 u; u.x = *(uint32_t*)&p0; u.y = *(uint32_t*)&p1;
    *(uint2*)(&g_nnb[side][(size_t)m*DIMK + d]) = u;
}

/* ------------------------------------------------------------------ */
/* 6. FUSED bf16 HMMA logits GEMM + sum-exp per row (split-K chains)   */
/* ------------------------------------------------------------------ */
__global__ void __launch_bounds__(256)
k_lse2()
{
    extern __shared__ __align__(16) char smem[];
    const int side = blockIdx.z, mt = blockIdx.y, rs = blockIdx.x;
    int tid = threadIdx.x, wid = tid >> 5, lane = tid & 31;
    uint32_t sb = smem_u32(smem);
    const uint32_t sbA = sb, sbB = sb + 32768;

    const float* Af = g_fn[side] + (size_t)mt * 128 * DIMK;
    #pragma unroll
    for (int j = 0; j < 8; j++) {
        int idx = tid + j*256;
        int m = idx >> 4, kc = idx & 15;
        const float* p = Af + m*DIMK + kc*8;
        float4 f0 = *(const float4*)p;
        float4 f1 = *(const float4*)(p + 4);
        *(uint4*)(smem + m*256 + ((kc ^ (m & 7)))*16) = cvt8(f0, f1);
    }
    __syncthreads();

    uint32_t a[8][4];
    {
        int m = wid*16 + (lane & 15);
        #pragma unroll
        for (int ks = 0; ks < 8; ks++) {
            int kc = ks*2 + (lane >> 4);
            uint32_t addr = sbA + m*256 + ((kc ^ (m & 7)))*16;
            LDSM4(a[ks][0], a[ks][1], a[ks][2], a[ks][3], addr);
        }
    }

    const __nv_bfloat16* NB = g_nnb[side];
    float S0 = 0.f, S1 = 0.f;

    for (int t = 0; t < NT2; t++) {
        __syncthreads();                   /* prev tile reads done */
        int c0 = (rs * NT2 + t) * 128;
        #pragma unroll
        for (int j = 0; j < 8; j++) {
            int idx = tid + j*256;
            int n = idx >> 4, kc = idx & 15;
            uint4 u = *(const uint4*)(NB + (size_t)(c0 + n)*DIMK + kc*8);
            *(uint4*)(smem + 32768 + n*256 + ((kc ^ (n & 7)))*16) = u;
        }
        __syncthreads();

        #pragma unroll 2
        for (int nt = 0; nt < 16; nt++) {
            uint32_t b[16];
            #pragma unroll
            for (int kb = 0; kb < 4; kb++) {
                int n = nt*8 + (lane & 7);
                int kc = kb*4 + (lane >> 3);
                uint32_t addr = sbB + n*256 + ((kc ^ (n & 7)))*16;
                LDSM4(b[kb*4+0], b[kb*4+1], b[kb*4+2], b[kb*4+3], addr);
            }
            float A0 = 0.f, A1 = 0.f, A2 = 0.f, A3 = 0.f;
            float B0 = 0.f, B1 = 0.f, B2 = 0.f, B3 = 0.f;
            #pragma unroll
            for (int ks = 0; ks < 4; ks++) {
                MMA16816(A0, A1, A2, A3,
                         a[ks][0], a[ks][1], a[ks][2], a[ks][3],
                         b[ks*2], b[ks*2+1]);
                MMA16816(B0, B1, B2, B3,
                         a[ks+4][0], a[ks+4][1], a[ks+4][2], a[ks+4][3],
                         b[(ks+4)*2], b[(ks+4)*2+1]);
            }
            S0 += __expf((A0 + B0)*INVT) + __expf((A1 + B1)*INVT);
            S1 += __expf((A2 + B2)*INVT) + __expf((A3 + B3)*INVT);
        }
    }

    #pragma unroll
    for (int o = 1; o <= 2; o <<= 1) {
        S0 += __shfl_xor_sync(0xFFFFFFFFu, S0, o);
        S1 += __shfl_xor_sync(0xFFFFFFFFu, S1, o);
    }
    int g = lane >> 2, q = lane & 3;
    if (q == 0) {
        int row = (side*8 + mt)*128 + wid*16 + g;
        g_S[(size_t)row*NSPL2 + rs]       = S0;
        g_S[(size_t)(row+8)*NSPL2 + rs]   = S1;
    }
}

/* ------------------------------------------------------------------ */
/* 7. positive logits                                                  */
/* ------------------------------------------------------------------ */
__global__ void k_pos()
{
    int b = blockIdx.x, side = blockIdx.y;
    int j = threadIdx.x >> 5, lane = threadIdx.x & 31;
    int m = b*NN + j;
    const float* f = g_fn[side] + b*DIMK;
    const __nv_bfloat16* nb = g_nnb[side] + (size_t)m * DIMK;
    float s = 0.f;
    #pragma unroll
    for (int d = lane; d < DIMK; d += 32)
        s += f[d] * __bfloat162float(nb[d]);
    #pragma unroll
    for (int o = 16; o; o >>= 1) s += __shfl_xor_sync(0xFFFFFFFFu, s, o);
    __shared__ float pj[NN];
    if (lane == 0) pj[j] = s;
    __syncthreads();
    if (threadIdx.x == 0) {
        float t = 0.f;
        #pragma unroll
        for (int qq = 0; qq < NN; qq++) t += pj[qq];
        g_pos[side*BB + b] = t * INVT;
    }
}

/* ------------------------------------------------------------------ */
/* 8. final loss                                                       */
/* ------------------------------------------------------------------ */
__global__ void k_loss(float* __restrict__ out)
{
    int tid = threadIdx.x;
    float a = 0.f;
    for (int r = tid; r < 2048; r += 256) {
        float S = 0.f;
        #pragma unroll
        for (int s = 0; s < NSPL2; s++) S += g_S[(size_t)r*NSPL2 + s];
        a += 10.0f * logf(S) - g_pos[r];
    }
    #pragma unroll
    for (int o = 16; o; o >>= 1) a += __shfl_xor_sync(0xFFFFFFFFu, a, o);
    __shared__ float w[8];
    if ((tid & 31) == 0) w[tid >> 5] = a;
    __syncthreads();
    if (tid == 0) {
        float t = 0.f;
        #pragma unroll
        for (int i = 0; i < 8; i++) t += w[i];
        out[0] = t / (float)BB;
    }
}

/* ------------------------------------------------------------------ */
extern "C" void kernel_launch(void* const* d_in, const int* in_sizes, int n_in,
                              void* d_out, int out_size)
{
    const float* fX = (const float*)d_in[0];
    const float* fY = (const float*)d_in[1];
    const float* qX = (const float*)d_in[2];
    const float* qY = (const float*)d_in[3];
    float* out = (float*)d_out;

    cudaFuncSetAttribute(k_simtopk, cudaFuncAttributeMaxDynamicSharedMemorySize, SMEM1);
    cudaFuncSetAttribute(k_lse2,    cudaFuncAttributeMaxDynamicSharedMemorySize, SMEM2);

    k_normalize<<<dim3(BB, 2), DIMK>>>(fX, fY, out);
    k_prep    <<<dim3(RQ/2/256, DIMK, 2), 256>>>(qX, qY);       /* one fused launch */
    k_simtopk <<<dim3(NSPL1, 8, 2), 256, SMEM1>>>(qX, qY, out);
    k_merge   <<<256, 256>>>();
    k_gather  <<<dim3(NM/8, 2), 256>>>(qX, qY);
    k_lse2    <<<dim3(NSPL2, 8, 2), 256, SMEM2>>>();
    k_pos     <<<dim3(BB, 2), 320>>>();
    k_loss    <<<1, 256>>>(out);
}

// round 14
// speedup vs baseline: 1.6808x; 1.6808x over previous
#include <cuda_runtime.h>
#include <cuda_bf16.h>
#include <math.h>
#include <stdint.h>

#define DIMK 128
#define RQ   131072
#define BB   1024
#define NN   10
#define NM   (BB*NN)          /* 10240 */
#define INVT 10.0f
#define NSPL1 26              /* phase-1 splits: uneven 40/39 tiles, grid 416 */
#define NTILES (RQ/128)       /* 1024 col-tiles per side */
#define NSPL2 10
#define NT2   8

#define SMEM1 65536           /* B0 32K | B1/Astage 32K (overlapped) */
#define SMEM2 65536

/* ------------------------- asm helpers ---------------------------- */
__device__ __forceinline__ uint32_t smem_u32(const void* p) {
    uint32_t a;
    asm("{ .reg .u64 t; cvta.to.shared.u64 t, %1; cvt.u32.u64 %0, t; }"
        : "=r"(a) : "l"(p));
    return a;
}
#define LDSM4(r0,r1,r2,r3, a) \
    asm volatile("ldmatrix.sync.aligned.m8n8.x4.shared.b16 {%0,%1,%2,%3}, [%4];" \
        : "=r"(r0),"=r"(r1),"=r"(r2),"=r"(r3) : "r"(a))
#define LDSM4T(r0,r1,r2,r3, a) \
    asm volatile("ldmatrix.sync.aligned.m8n8.x4.trans.shared.b16 {%0,%1,%2,%3}, [%4];" \
        : "=r"(r0),"=r"(r1),"=r"(r2),"=r"(r3) : "r"(a))
#define MMA16816(c0,c1,c2,c3, a0,a1,a2,a3, b0,b1) \
    asm volatile("mma.sync.aligned.m16n8k16.row.col.f32.bf16.bf16.f32 " \
        "{%0,%1,%2,%3}, {%4,%5,%6,%7}, {%8,%9}, {%0,%1,%2,%3};" \
        : "+f"(c0),"+f"(c1),"+f"(c2),"+f"(c3) \
        : "r"(a0),"r"(a1),"r"(a2),"r"(a3),"r"(b0),"r"(b1))
#define CPA16(dst, src) \
    asm volatile("cp.async.cg.shared.global [%0], [%1], 16;" \
        :: "r"(dst), "l"(src) : "memory")
#define CPA_COMMIT() asm volatile("cp.async.commit_group;" ::: "memory")
#define CPA_WAIT0()  asm volatile("cp.async.wait_group 0;" ::: "memory")

/* packed-key insert: signed-int compare on (valbits19 | colcomp13) keys */
#define UINS(V, s) do {                                                \
    if ((int)(s) > (int)V[9]) {                                        \
        V[9] = (s);                                                    \
        _Pragma("unroll")                                              \
        for (int _j = 9; _j > 0; _j--)                                 \
            if ((int)V[_j] > (int)V[_j-1]) {                           \
                uint32_t _t = V[_j]; V[_j] = V[_j-1]; V[_j-1] = _t;    \
            }                                                          \
    } } while (0)

__device__ __forceinline__ uint4 cvt8(float4 a, float4 b) {
    __nv_bfloat162 p0 = __float22bfloat162_rn(make_float2(a.x, a.y));
    __nv_bfloat162 p1 = __float22bfloat162_rn(make_float2(a.z, a.w));
    __nv_bfloat162 p2 = __float22bfloat162_rn(make_float2(b.x, b.y));
    __nv_bfloat162 p3 = __float22bfloat162_rn(make_float2(b.z, b.w));
    uint4 u;
    u.x = *(uint32_t*)&p0; u.y = *(uint32_t*)&p1;
    u.z = *(uint32_t*)&p2; u.w = *(uint32_t*)&p3;
    return u;
}
__device__ __forceinline__ uint32_t packkey(float s, int colcomp) {
    return (__float_as_uint(s) & 0xFFFFE000u) | (uint32_t)colcomp;
}

/* -------------------------- scratch ------------------------------- */
__device__ float g_fn[2][BB*DIMK];
__device__ __nv_bfloat16 g_qb[2][(size_t)DIMK*RQ];    /* g_qb[side] = CROSS queue */
__device__ uint32_t g_ptk[2048*NSPL1*NN];             /* packed partial top-10 keys */
__device__ int   g_topk[2*NM];
__device__ __nv_bfloat16 g_nnb[2][(size_t)NM*DIMK];   /* [m][k] bf16 */
__device__ float g_S[2048*NSPL2];
__device__ float g_pos[2*BB];

/* ------------------------------------------------------------------ */
/* 1. row-normalize feats; scatter f.T into output queue[:, :B]        */
/* ------------------------------------------------------------------ */
__global__ void k_normalize(const float* __restrict__ fX,
                            const float* __restrict__ fY,
                            float* __restrict__ out)
{
    int b = blockIdx.x, side = blockIdx.y, d = threadIdx.x;
    const float* src = side ? fY : fX;
    float v = src[b*DIMK + d];
    float ss = v*v;
    #pragma unroll
    for (int o = 16; o; o >>= 1) ss += __shfl_xor_sync(0xFFFFFFFFu, ss, o);
    __shared__ float ws[4];
    if ((d & 31) == 0) ws[d >> 5] = ss;
    __syncthreads();
    float inv = rsqrtf(ws[0] + ws[1] + ws[2] + ws[3]);
    float w = v * inv;
    g_fn[side][b*DIMK + d] = w;
    float* q = out + 1 + (size_t)side * DIMK * RQ;
    q[(size_t)d * RQ + b] = w;
}

/* ------------------------------------------------------------------ */
/* 2. prep: one read of each queue -> bf16 CROSS cache + fp32 out copy */
/* ------------------------------------------------------------------ */
__global__ void k_prep(const float* __restrict__ qX,
                       const float* __restrict__ qY,
                       float* __restrict__ out)
{
    int side = blockIdx.z, d = blockIdx.y;
    int c = 2 * (blockIdx.x * blockDim.x + threadIdx.x);
    const float* q = side ? qY : qX;
    size_t off = (size_t)d * RQ + c;
    float2 v = *(const float2*)(q + off);
    *(__nv_bfloat162*)(&g_qb[side ^ 1][off]) = __float22bfloat162_rn(v);
    if (c >= BB) {
        float* o = out + 1 + (size_t)side * DIMK * RQ + off;
        o[0] = v.x; o[1] = v.y;
    }
}

/* ------------------------------------------------------------------ */
/* 3. FUSED bf16 HMMA sim GEMM + per-row top-10 — occ-3 experiment:    */
/*    64K smem (A overlaps B1), packed 32-bit keys, forced 3 CTA/SM    */
/* ------------------------------------------------------------------ */
__global__ void __launch_bounds__(256, 3)
k_simtopk()
{
    extern __shared__ __align__(16) char smem[];
    const int side = blockIdx.z, mt = blockIdx.y, rs = blockIdx.x;
    const __nv_bfloat16* Q = g_qb[side];
    int tid = threadIdx.x, wid = tid >> 5, lane = tid & 31;
    uint32_t sb = smem_u32(smem);
    const int t_lo = (rs * NTILES) / NSPL1;
    const int t_hi = ((rs + 1) * NTILES) / NSPL1;
    const int ntc = t_hi - t_lo;                  /* 39 or 40 */

    /* async-stage B global tile gt into buffer buf (0/1) */
    auto stage_b = [&](int buf, int gt) {
        int c0 = gt * 128;
        uint32_t dstbase = sb + buf * 32768;
        #pragma unroll
        for (int j = 0; j < 8; j++) {
            int idx = tid + j*256;
            int k = idx >> 4, nc = idx & 15;
            uint32_t dst = dstbase + k*256 + ((nc ^ (k & 7)))*16;
            CPA16(dst, (const void*)(Q + (size_t)k*RQ + c0 + nc*8));
        }
        CPA_COMMIT();
    };

    stage_b(0, t_lo);                      /* B0 -> [0,32K) */

    /* stage A into upper half [32K,64K) — reused by B1 after frag load */
    const float* Af = g_fn[side] + (size_t)mt * 128 * DIMK;
    #pragma unroll
    for (int j = 0; j < 8; j++) {
        int idx = tid + j*256;
        int m = idx >> 4, kc = idx & 15;
        const float* p = Af + m*DIMK + kc*8;
        float4 f0 = *(const float4*)p;
        float4 f1 = *(const float4*)(p + 4);
        *(uint4*)(smem + 32768 + m*256 + ((kc ^ (m & 7)))*16) = cvt8(f0, f1);
    }

    CPA_WAIT0();
    __syncthreads();                       /* A + B0 ready */

    uint32_t a[8][4];
    {
        int m = wid*16 + (lane & 15);
        #pragma unroll
        for (int ks = 0; ks < 8; ks++) {
            int kc = ks*2 + (lane >> 4);
            uint32_t addr = sb + 32768 + m*256 + ((kc ^ (m & 7)))*16;
            LDSM4(a[ks][0], a[ks][1], a[ks][2], a[ks][3], addr);
        }
    }
    __syncthreads();                       /* A reads done -> B1 may overwrite */

    uint32_t k0[10], k1[10];
    #pragma unroll
    for (int i = 0; i < 10; i++) { k0[i] = 0u; k1[i] = 0u; }
    const int coff = 2*(lane & 3);

    for (int t = 0; t < ntc; t++) {
        uint32_t bufa = sb + (t & 1) * 32768;
        if (t + 1 < ntc) stage_b((t + 1) & 1, t_lo + t + 1);
        int ccomp = 8191 - (t*128 + coff);         /* complemented local col */
        #pragma unroll 2
        for (int nt = 0; nt < 16; nt++) {
            uint32_t b[16];
            #pragma unroll
            for (int kb = 0; kb < 4; kb++) {
                int krow = kb*32 + lane;
                uint32_t addr = bufa + krow*256 + ((nt ^ (krow & 7)))*16;
                LDSM4T(b[kb*4+0], b[kb*4+1], b[kb*4+2], b[kb*4+3], addr);
            }
            float c0 = 0.f, c1 = 0.f, c2 = 0.f, c3 = 0.f;
            #pragma unroll
            for (int ks = 0; ks < 8; ks++)
                MMA16816(c0, c1, c2, c3,
                         a[ks][0], a[ks][1], a[ks][2], a[ks][3],
                         b[ks*2], b[ks*2+1]);
            int cc = ccomp - nt*8;
            uint32_t p0 = packkey(c0, cc),   p1 = packkey(c1, cc-1);
            uint32_t p2 = packkey(c2, cc),   p3 = packkey(c3, cc-1);
            if (max((int)p0, (int)p1) > (int)k0[9]) { UINS(k0, p0); UINS(k0, p1); }
            if (max((int)p2, (int)p3) > (int)k1[9]) { UINS(k1, p2); UINS(k1, p3); }
        }
        if (t + 1 < ntc) { CPA_WAIT0(); __syncthreads(); }
    }

    /* quad merge on keys: lanes (l&3)=0..3 share rows g, g+8 */
    int g = lane >> 2, q = lane & 3;
    #pragma unroll
    for (int listid = 0; listid < 2; listid++) {
        uint32_t* v = listid ? k1 : k0;
        int row = (side*8 + mt)*128 + wid*16 + g + listid*8;
        #pragma unroll
        for (int k = 0; k < 10; k++) {
            uint32_t bk = v[0]; int bq = q;
            #pragma unroll
            for (int o = 1; o <= 2; o <<= 1) {
                uint32_t ok = __shfl_xor_sync(0xFFFFFFFFu, bk, o);
                int oq = __shfl_xor_sync(0xFFFFFFFFu, bq, o);
                if ((int)ok > (int)bk) { bk = ok; bq = oq; }
            }
            if (q == 0) g_ptk[((size_t)row*NSPL1 + rs)*NN + k] = bk;
            if (q == bq) {
                #pragma unroll
                for (int j = 0; j < 9; j++) v[j] = v[j+1];
                v[9] = 0u;
            }
        }
    }
}

/* ------------------------------------------------------------------ */
/* 4. merge NSPL1 packed partial lists per row (warp per row)          */
/* ------------------------------------------------------------------ */
__global__ void k_merge()
{
    int rg = blockIdx.x * 8 + (threadIdx.x >> 5);
    int lane = threadIdx.x & 31;
    uint32_t v[10];
    if (lane < NSPL1) {
        const uint32_t* pk = g_ptk + ((size_t)rg*NSPL1 + lane)*NN;
        #pragma unroll
        for (int k = 0; k < 10; k++) v[k] = pk[k];
    } else {
        #pragma unroll
        for (int k = 0; k < 10; k++) v[k] = 0u;
    }
    #pragma unroll
    for (int k = 0; k < 10; k++) {
        uint32_t bk = v[0]; int bl = lane;
        #pragma unroll
        for (int o = 1; o <= 16; o <<= 1) {
            uint32_t ok = __shfl_xor_sync(0xFFFFFFFFu, bk, o);
            int ol = __shfl_xor_sync(0xFFFFFFFFu, bl, o);
            if ((int)ok > (int)bk) { bk = ok; bl = ol; }
        }
        if (lane == 0) {
            int c_lo = ((bl * NTILES) / NSPL1) * 128;
            int lcol = 8191 - (int)(bk & 0x1FFFu);
            g_topk[rg*NN + k] = c_lo + lcol;
        }
        if (lane == bl) {
            #pragma unroll
            for (int j = 0; j < 9; j++) v[j] = v[j+1];
            v[9] = 0u;
        }
    }
}

/* ------------------------------------------------------------------ */
/* 5. gather neighbors as bf16 [m][k] (from fp32 CROSS queue)          */
/* ------------------------------------------------------------------ */
__global__ void k_gather(const float* __restrict__ qX,
                         const float* __restrict__ qY)
{
    int side = blockIdx.y;
    int m = blockIdx.x * 8 + (threadIdx.x >> 5);
    int d = (threadIdx.x & 31) * 4;
    const float* Q = side ? qX : qY;
    int idx = g_topk[side*NM + m];
    float a0 = Q[(size_t)(d+0)*RQ + idx];
    float a1 = Q[(size_t)(d+1)*RQ + idx];
    float a2 = Q[(size_t)(d+2)*RQ + idx];
    float a3 = Q[(size_t)(d+3)*RQ + idx];
    __nv_bfloat162 p0 = __float22bfloat162_rn(make_float2(a0, a1));
    __nv_bfloat162 p1 = __float22bfloat162_rn(make_float2(a2, a3));
    uint2 u; u.x = *(uint32_t*)&p0; u.y = *(uint32_t*)&p1;
    *(uint2*)(&g_nnb[side][(size_t)m*DIMK + d]) = u;
}

/* ------------------------------------------------------------------ */
/* 6. FUSED bf16 HMMA logits GEMM + sum-exp per row                    */
/* ------------------------------------------------------------------ */
__global__ void __launch_bounds__(256)
k_lse2()
{
    extern __shared__ __align__(16) char smem[];
    const int side = blockIdx.z, mt = blockIdx.y, rs = blockIdx.x;
    int tid = threadIdx.x, wid = tid >> 5, lane = tid & 31;
    uint32_t sb = smem_u32(smem);
    const uint32_t sbA = sb, sbB = sb + 32768;

    const float* Af = g_fn[side] + (size_t)mt * 128 * DIMK;
    #pragma unroll
    for (int j = 0; j < 8; j++) {
        int idx = tid + j*256;
        int m = idx >> 4, kc = idx & 15;
        const float* p = Af + m*DIMK + kc*8;
        float4 f0 = *(const float4*)p;
        float4 f1 = *(const float4*)(p + 4);
        *(uint4*)(smem + m*256 + ((kc ^ (m & 7)))*16) = cvt8(f0, f1);
    }
    __syncthreads();

    uint32_t a[8][4];
    {
        int m = wid*16 + (lane & 15);
        #pragma unroll
        for (int ks = 0; ks < 8; ks++) {
            int kc = ks*2 + (lane >> 4);
            uint32_t addr = sbA + m*256 + ((kc ^ (m & 7)))*16;
            LDSM4(a[ks][0], a[ks][1], a[ks][2], a[ks][3], addr);
        }
    }

    const __nv_bfloat16* NB = g_nnb[side];
    float S0 = 0.f, S1 = 0.f;

    for (int t = 0; t < NT2; t++) {
        __syncthreads();
        int c0 = (rs * NT2 + t) * 128;
        #pragma unroll
        for (int j = 0; j < 8; j++) {
            int idx = tid + j*256;
            int n = idx >> 4, kc = idx & 15;
            uint4 u = *(const uint4*)(NB + (size_t)(c0 + n)*DIMK + kc*8);
            *(uint4*)(smem + 32768 + n*256 + ((kc ^ (n & 7)))*16) = u;
        }
        __syncthreads();

        #pragma unroll 2
        for (int nt = 0; nt < 16; nt++) {
            uint32_t b[16];
            #pragma unroll
            for (int kb = 0; kb < 4; kb++) {
                int n = nt*8 + (lane & 7);
                int kc = kb*4 + (lane >> 3);
                uint32_t addr = sbB + n*256 + ((kc ^ (n & 7)))*16;
                LDSM4(b[kb*4+0], b[kb*4+1], b[kb*4+2], b[kb*4+3], addr);
            }
            float A0 = 0.f, A1 = 0.f, A2 = 0.f, A3 = 0.f;
            #pragma unroll
            for (int ks = 0; ks < 8; ks++)
                MMA16816(A0, A1, A2, A3,
                         a[ks][0], a[ks][1], a[ks][2], a[ks][3],
                         b[ks*2], b[ks*2+1]);
            S0 += __expf(A0*INVT) + __expf(A1*INVT);
            S1 += __expf(A2*INVT) + __expf(A3*INVT);
        }
    }

    #pragma unroll
    for (int o = 1; o <= 2; o <<= 1) {
        S0 += __shfl_xor_sync(0xFFFFFFFFu, S0, o);
        S1 += __shfl_xor_sync(0xFFFFFFFFu, S1, o);
    }
    int g = lane >> 2, q = lane & 3;
    if (q == 0) {
        int row = (side*8 + mt)*128 + wid*16 + g;
        g_S[(size_t)row*NSPL2 + rs]       = S0;
        g_S[(size_t)(row+8)*NSPL2 + rs]   = S1;
    }
}

/* ------------------------------------------------------------------ */
/* 7. positive logits                                                  */
/* ------------------------------------------------------------------ */
__global__ void k_pos()
{
    int b = blockIdx.x, side = blockIdx.y;
    int j = threadIdx.x >> 5, lane = threadIdx.x & 31;
    int m = b*NN + j;
    const float* f = g_fn[side] + b*DIMK;
    const __nv_bfloat16* nb = g_nnb[side] + (size_t)m * DIMK;
    float s = 0.f;
    #pragma unroll
    for (int d = lane; d < DIMK; d += 32)
        s += f[d] * __bfloat162float(nb[d]);
    #pragma unroll
    for (int o = 16; o; o >>= 1) s += __shfl_xor_sync(0xFFFFFFFFu, s, o);
    __shared__ float pj[NN];
    if (lane == 0) pj[j] = s;
    __syncthreads();
    if (threadIdx.x == 0) {
        float t = 0.f;
        #pragma unroll
        for (int qq = 0; qq < NN; qq++) t += pj[qq];
        g_pos[side*BB + b] = t * INVT;
    }
}

/* ------------------------------------------------------------------ */
/* 8. final loss                                                       */
/* ------------------------------------------------------------------ */
__global__ void k_loss(float* __restrict__ out)
{
    int tid = threadIdx.x;
    float a = 0.f;
    for (int r = tid; r < 2048; r += 256) {
        float S = 0.f;
        #pragma unroll
        for (int s = 0; s < NSPL2; s++) S += g_S[(size_t)r*NSPL2 + s];
        a += 10.0f * logf(S) - g_pos[r];
    }
    #pragma unroll
    for (int o = 16; o; o >>= 1) a += __shfl_xor_sync(0xFFFFFFFFu, a, o);
    __shared__ float w[8];
    if ((tid & 31) == 0) w[tid >> 5] = a;
    __syncthreads();
    if (tid == 0) {
        float t = 0.f;
        #pragma unroll
        for (int i = 0; i < 8; i++) t += w[i];
        out[0] = t / (float)BB;
    }
}

/* ------------------------------------------------------------------ */
extern "C" void kernel_launch(void* const* d_in, const int* in_sizes, int n_in,
                              void* d_out, int out_size)
{
    const float* fX = (const float*)d_in[0];
    const float* fY = (const float*)d_in[1];
    const float* qX = (const float*)d_in[2];
    const float* qY = (const float*)d_in[3];
    float* out = (float*)d_out;

    cudaFuncSetAttribute(k_simtopk, cudaFuncAttributeMaxDynamicSharedMemorySize, SMEM1);
    cudaFuncSetAttribute(k_lse2,    cudaFuncAttributeMaxDynamicSharedMemorySize, SMEM2);

    k_normalize<<<dim3(BB, 2), DIMK>>>(fX, fY, out);
    k_prep    <<<dim3(RQ/2/256, DIMK, 2), 256>>>(qX, qY, out);
    k_simtopk <<<dim3(NSPL1, 8, 2), 256, SMEM1>>>();
    k_merge   <<<256, 256>>>();
    k_gather  <<<dim3(NM/8, 2), 256>>>(qX, qY);
    k_lse2    <<<dim3(NSPL2, 8, 2), 256, SMEM2>>>();
    k_pos     <<<dim3(BB, 2), 320>>>();
    k_loss    <<<1, 256>>>(out);
}